// round 5
// baseline (speedup 1.0000x reference)
#include <cuda_runtime.h>
#include <cuda_bf16.h>
#include <math.h>

#define SS 512
#define BB 128
#define EE 128
#define HH 128
#define KK 32
#define TAG_START 30
#define TAG_END 31

// ----------------------------- device scratch ------------------------------
__device__ float g_xW[(size_t)SS * BB * 1024];   // [s*B+b][d*512 + g*128 + u]
__device__ float g_hs[2][(size_t)SS * BB * HH];  // per-dir h at original time
__device__ float g_feats[(size_t)BB * SS * KK];  // [b][s][k]
__device__ float g_num[BB];
__device__ float g_den[BB];

// ----------------------------- helpers -------------------------------------
__device__ __forceinline__ void fma2(unsigned long long& d, unsigned long long a,
                                     unsigned long long b) {
  asm("fma.rn.f32x2 %0, %1, %2, %0;" : "+l"(d) : "l"(a), "l"(b));
}
__device__ __forceinline__ unsigned long long pack2(float x, float y) {
  unsigned long long r;
  asm("mov.b64 %0, {%1, %2};" : "=l"(r) : "f"(x), "f"(y));
  return r;
}
__device__ __forceinline__ float plo(unsigned long long v) {
  return __uint_as_float((unsigned)v);
}
__device__ __forceinline__ float phi(unsigned long long v) {
  return __uint_as_float((unsigned)(v >> 32));
}
__device__ __forceinline__ float sigm(float x) {
  return __fdividef(1.f, 1.f + __expf(-x));
}
__device__ __forceinline__ float ftanh(float x) {
  float e = __expf(-2.f * fmaxf(x, -20.f));
  return __fdividef(1.f - e, 1.f + e);
}

#define CLUSTER_SYNC()                                              \
  do {                                                              \
    asm volatile("barrier.cluster.arrive.aligned;" ::: "memory");   \
    asm volatile("barrier.cluster.wait.aligned;" ::: "memory");     \
  } while (0)

// ------------- 1) fused embedding + input GEMM: xW = X @ Wih^T + b ---------
// M = S*B = 65536, N = 1024 (fwd 512 | bwd 512), K = 128.
// 128x64 block tile, 8x4 thread tile, f32x2 packed FMA.
__global__ void __launch_bounds__(256) gemm_xw_k(
    const int* __restrict__ sentence, const float* __restrict__ table,
    const float* __restrict__ Wf, const float* __restrict__ Wb,
    const float* __restrict__ bihf, const float* __restrict__ bhhf,
    const float* __restrict__ bihb, const float* __restrict__ bhhb) {
  __shared__ __align__(16) float As[32 * 132];  // [k][m] padded
  __shared__ __align__(16) float Bs[32 * 68];   // [k][n] padded
  int tid = threadIdx.x;
  int bm = blockIdx.x, bn = blockIdx.y;
  int r0 = bm * 128, n0 = bn * 64;
  int tx = tid & 15, ty = tid >> 4;

  // A loader: 2 threads per row, 16 k each
  int arow = tid >> 1, akh = (tid & 1) * 16;
  int r = r0 + arow;
  int s = r >> 7, b = r & 127;
  const float* asrc = table + (size_t)sentence[b * SS + s] * EE;
  // B loader: 4 threads per row, 8 k each
  int brow = tid >> 2, bkq = (tid & 3) * 8;
  int jg = n0 + brow;
  const float* wsrc = (jg < 512) ? Wf + (size_t)jg * EE
                                 : Wb + (size_t)(jg - 512) * EE;

  unsigned long long acc2[8][2];
#pragma unroll
  for (int i = 0; i < 8; i++) { acc2[i][0] = 0ull; acc2[i][1] = 0ull; }

  for (int kt = 0; kt < 4; kt++) {
    int kb = kt * 32;
#pragma unroll
    for (int q = 0; q < 4; q++) {
      float4 v = *(const float4*)(asrc + kb + akh + q * 4);
      As[(akh + q * 4 + 0) * 132 + arow] = v.x;
      As[(akh + q * 4 + 1) * 132 + arow] = v.y;
      As[(akh + q * 4 + 2) * 132 + arow] = v.z;
      As[(akh + q * 4 + 3) * 132 + arow] = v.w;
    }
#pragma unroll
    for (int q = 0; q < 2; q++) {
      float4 v = *(const float4*)(wsrc + kb + bkq + q * 4);
      Bs[(bkq + q * 4 + 0) * 68 + brow] = v.x;
      Bs[(bkq + q * 4 + 1) * 68 + brow] = v.y;
      Bs[(bkq + q * 4 + 2) * 68 + brow] = v.z;
      Bs[(bkq + q * 4 + 3) * 68 + brow] = v.w;
    }
    __syncthreads();
#pragma unroll
    for (int kk = 0; kk < 32; kk++) {
      float4 a0 = *(const float4*)&As[kk * 132 + ty * 8];
      float4 a1 = *(const float4*)&As[kk * 132 + ty * 8 + 4];
      ulonglong2 bp = *(const ulonglong2*)&Bs[kk * 68 + tx * 4];
      const float* ap0 = (const float*)&a0;
      const float* ap1 = (const float*)&a1;
#pragma unroll
      for (int i = 0; i < 4; i++) {
        unsigned long long aa = pack2(ap0[i], ap0[i]);
        fma2(acc2[i][0], aa, bp.x);
        fma2(acc2[i][1], aa, bp.y);
        unsigned long long ab = pack2(ap1[i], ap1[i]);
        fma2(acc2[4 + i][0], ab, bp.x);
        fma2(acc2[4 + i][1], ab, bp.y);
      }
    }
    __syncthreads();
  }
  float bias[4];
#pragma unroll
  for (int jj = 0; jj < 4; jj++) {
    int j = n0 + tx * 4 + jj;
    bias[jj] = (j < 512) ? (bihf[j] + bhhf[j]) : (bihb[j - 512] + bhhb[j - 512]);
  }
  int n = n0 + tx * 4;
#pragma unroll
  for (int ii = 0; ii < 8; ii++) {
    int m = r0 + ty * 8 + ii;
    float4 o;
    o.x = plo(acc2[ii][0]) + bias[0];
    o.y = phi(acc2[ii][0]) + bias[1];
    o.z = plo(acc2[ii][1]) + bias[2];
    o.w = phi(acc2[ii][1]) + bias[3];
    *(float4*)&g_xW[(size_t)m * 1024 + n] = o;
  }
}

// --------------- 2) bidirectional LSTM recurrence (cluster pairs) ----------
// 64 clusters of 2 CTAs; cluster = (dir, 4-batch tile); CTA = u-half.
// W_hh slice lives permanently in registers (128 floats/thread).
// h exchanged via DSMEM store + barrier.cluster each step.
__global__ void __cluster_dims__(2, 1, 1) __launch_bounds__(256, 1) lstm_k(
    const float* __restrict__ Whhf, const float* __restrict__ Whhb,
    const float* __restrict__ h0, const float* __restrict__ c0) {
  __shared__ __align__(16) float hb[2][4 * 132];  // [parity][b_local*132 + u]
  int rank = blockIdx.x & 1;
  int cl = blockIdx.x >> 1;
  int d = cl >> 5;
  int b0 = (cl & 31) * 4;
  int tid = threadIdx.x;
  int lane = tid & 31;
  int wid = tid >> 5;
  int ks = lane >> 3;                 // k-slice / batch-local index 0..3
  int ulg = wid * 8 + (lane & 7);     // 0..63
  int u = rank * 64 + ulg;

  const float* Whh = d ? Whhb : Whhf;
  // register-resident weights: w2[g][i] covers k = ks*32 + 2i, 2i+1
  unsigned long long w2[4][16];
#pragma unroll
  for (int g = 0; g < 4; g++) {
    const float* wr = Whh + (size_t)(g * 128 + u) * 128 + ks * 32;
#pragma unroll
    for (int q = 0; q < 8; q++) {
      ulonglong2 v = *(const ulonglong2*)(wr + q * 4);
      w2[g][q * 2] = v.x;
      w2[g][q * 2 + 1] = v.y;
    }
  }
  // init h (full 128 u per batch, local copy)
  for (int i = tid; i < 512; i += 256) {
    int j = i >> 7, uu = i & 127;
    hb[0][j * 132 + uu] = h0[(d * BB + b0 + j) * HH + uu];
  }
  float c = c0[(d * BB + b0 + ks) * HH + u];

  unsigned hb_u32;
  asm("{ .reg .u64 t; cvta.to.shared.u64 t, %1; cvt.u32.u64 %0, t; }"
      : "=r"(hb_u32) : "l"(&hb[0][0]));
  unsigned peer_base;
  asm("mapa.shared::cluster.u32 %0, %1, %2;"
      : "=r"(peer_base) : "r"(hb_u32), "r"(rank ^ 1));

  __syncthreads();
  CLUSTER_SYNC();

  for (int t = 0; t < SS; t++) {
    const float* cur = hb[t & 1];
    int np = (t + 1) & 1;
    int tx = d ? (SS - 1 - t) : t;
    // prefetch xW (gate = ks) for 4 batches
    float xwv[4];
    const float* xwb =
        g_xW + ((size_t)tx * BB + b0) * 1024 + d * 512 + ks * 128 + u;
#pragma unroll
    for (int j = 0; j < 4; j++) xwv[j] = __ldcg(xwb + j * 1024);

    unsigned long long acc2[4][4];
#pragma unroll
    for (int j = 0; j < 4; j++)
#pragma unroll
      for (int g = 0; g < 4; g++) acc2[j][g] = 0ull;

#pragma unroll
    for (int q = 0; q < 8; q++) {
      int k = ks * 32 + q * 4;
      ulonglong2 hv[4];
#pragma unroll
      for (int j = 0; j < 4; j++)
        hv[j] = *(const ulonglong2*)&cur[j * 132 + k];
#pragma unroll
      for (int j = 0; j < 4; j++)
#pragma unroll
        for (int g = 0; g < 4; g++) {
          fma2(acc2[j][g], hv[j].x, w2[g][q * 2]);
          fma2(acc2[j][g], hv[j].y, w2[g][q * 2 + 1]);
        }
    }
    float acc[4][4];
#pragma unroll
    for (int j = 0; j < 4; j++)
#pragma unroll
      for (int g = 0; g < 4; g++) {
        float v = plo(acc2[j][g]) + phi(acc2[j][g]);
        if (g == ks) v += xwv[j];
        v += __shfl_xor_sync(0xffffffffu, v, 8);
        v += __shfl_xor_sync(0xffffffffu, v, 16);
        acc[j][g] = v;
      }
    // each lane handles batch j = ks
    float gate[4];
#pragma unroll
    for (int g = 0; g < 4; g++) {
      float a01 = (ks & 1) ? acc[1][g] : acc[0][g];
      float a23 = (ks & 1) ? acc[3][g] : acc[2][g];
      gate[g] = (ks & 2) ? a23 : a01;
    }
    float si = sigm(gate[0]);
    float sf = sigm(gate[1]);
    float tg = ftanh(gate[2]);
    float so = sigm(gate[3]);
    c = sf * c + si * tg;
    float h = so * ftanh(c);
    hb[np][ks * 132 + u] = h;
    unsigned pa = peer_base + (unsigned)(np * 528 + ks * 132 + u) * 4u;
    asm volatile("st.shared::cluster.f32 [%0], %1;" :: "r"(pa), "f"(h));
    g_hs[d][((size_t)tx * BB + b0 + ks) * HH + u] = h;
    CLUSTER_SYNC();
  }
}

// -------------- 3) feats = concat(hf,hb) @ Wout^T + bout -------------------
__global__ void __launch_bounds__(256) feats_k(const float* __restrict__ Wout,
                                               const float* __restrict__ bout) {
  __shared__ __align__(16) float Wsh[32 * 260];
  __shared__ float bsh[32];
  int s = blockIdx.x;
  int tid = threadIdx.x;
  for (int i = tid; i < 2048; i += 256) {
    int k = i >> 6, m4 = i & 63;
    float4 v = ((const float4*)Wout)[i];
    *(float4*)&Wsh[k * 260 + m4 * 4] = v;
  }
  if (tid < 32) bsh[tid] = bout[tid];
  __syncthreads();
  int k = tid & 31, b0 = tid >> 5;
  for (int bb = 0; bb < 16; bb++) {
    int b = b0 + bb * 8;
    const float4* hf = (const float4*)&g_hs[0][((size_t)s * BB + b) * HH];
    const float4* hb2 = (const float4*)&g_hs[1][((size_t)s * BB + b) * HH];
    float acc = bsh[k];
#pragma unroll 8
    for (int m4 = 0; m4 < 32; m4++) {
      float4 hv = hf[m4];
      float4 wv = *(const float4*)&Wsh[k * 260 + m4 * 4];
      acc += hv.x * wv.x + hv.y * wv.y + hv.z * wv.z + hv.w * wv.w;
    }
#pragma unroll 8
    for (int m4 = 0; m4 < 32; m4++) {
      float4 hv = hb2[m4];
      float4 wv = *(const float4*)&Wsh[k * 260 + 128 + m4 * 4];
      acc += hv.x * wv.x + hv.y * wv.y + hv.z * wv.z + hv.w * wv.w;
    }
    g_feats[((size_t)b * SS + s) * KK + k] = acc;
  }
}

// ----------------------------- 4) CRF numerator ----------------------------
__global__ void __launch_bounds__(128) numer_k(const int* __restrict__ tags,
                                               const float* __restrict__ T) {
  __shared__ float red[128];
  int b = blockIdx.x;
  int tid = threadIdx.x;
  float sum = 0.f;
  for (int s = tid; s < SS; s += 128) {
    int cur = tags[b * SS + s];
    int prev = (s == 0) ? TAG_START : tags[b * SS + s - 1];
    sum += T[prev * KK + cur] + g_feats[((size_t)b * SS + s) * KK + cur];
  }
  red[tid] = sum;
  __syncthreads();
  for (int off = 64; off > 0; off >>= 1) {
    if (tid < off) red[tid] += red[tid + off];
    __syncthreads();
  }
  if (tid == 0) g_num[b] = red[0] + T[tags[b * SS + SS - 1] * KK + TAG_END];
}

// ---------------------------- 5) CRF denominator ---------------------------
__global__ void __launch_bounds__(256) denom_k(const float* __restrict__ T) {
  __shared__ float Tsh[32 * 33];
  int tid = threadIdx.x;
  int lane = tid & 31;
  int warp = tid >> 5;
  int b = blockIdx.x * 8 + warp;
  for (int i = tid; i < 1024; i += 256) Tsh[(i >> 5) * 33 + (i & 31)] = T[i];
  __syncthreads();

  float alpha = (lane == TAG_START) ? 0.f : -10000.f;
  const float* Trow = &Tsh[lane * 33];
  for (int s = 0; s < SS; s++) {
    float feat = g_feats[((size_t)b * SS + s) * KK + lane];
    float tmp[32];
    float m = -3.0e38f;
#pragma unroll
    for (int p = 0; p < 32; p++) {
      float ap = __shfl_sync(0xffffffffu, alpha, p);
      tmp[p] = ap + Trow[p];
      m = fmaxf(m, tmp[p]);
    }
    float sum = 0.f;
#pragma unroll
    for (int p = 0; p < 32; p++) sum += __expf(tmp[p] - m);
    alpha = __logf(sum) + m + feat;
  }
  float v = alpha + Tsh[lane * 33 + TAG_END];
  float m2 = v;
#pragma unroll
  for (int o = 16; o > 0; o >>= 1)
    m2 = fmaxf(m2, __shfl_xor_sync(0xffffffffu, m2, o));
  float s2 = __expf(v - m2);
#pragma unroll
  for (int o = 16; o > 0; o >>= 1) s2 += __shfl_xor_sync(0xffffffffu, s2, o);
  if (lane == 0) g_den[b] = __logf(s2) + m2;
}

// --------------------------------- 6) mean ---------------------------------
__global__ void __launch_bounds__(128) mean_k(float* __restrict__ out) {
  __shared__ float red[128];
  int tid = threadIdx.x;
  red[tid] = g_num[tid] - g_den[tid];
  __syncthreads();
  for (int off = 64; off > 0; off >>= 1) {
    if (tid < off) red[tid] += red[tid + off];
    __syncthreads();
  }
  if (tid == 0) out[0] = red[0] / 128.0f;
}

// ------------------------------- launcher ----------------------------------
extern "C" void kernel_launch(void* const* d_in, const int* in_sizes, int n_in,
                              void* d_out, int out_size) {
  const int*   sentence = (const int*)d_in[0];
  const int*   tags     = (const int*)d_in[1];
  const float* table    = (const float*)d_in[2];
  const float* W_ih_f   = (const float*)d_in[3];
  const float* W_hh_f   = (const float*)d_in[4];
  const float* b_ih_f   = (const float*)d_in[5];
  const float* b_hh_f   = (const float*)d_in[6];
  const float* W_ih_b   = (const float*)d_in[7];
  const float* W_hh_b   = (const float*)d_in[8];
  const float* b_ih_b   = (const float*)d_in[9];
  const float* b_hh_b   = (const float*)d_in[10];
  const float* W_out    = (const float*)d_in[11];
  const float* b_out    = (const float*)d_in[12];
  const float* trans    = (const float*)d_in[13];
  const float* h0       = (const float*)d_in[14];
  const float* c0       = (const float*)d_in[15];
  float* out = (float*)d_out;

  gemm_xw_k<<<dim3(512, 16), 256>>>(sentence, table, W_ih_f, W_ih_b,
                                    b_ih_f, b_hh_f, b_ih_b, b_hh_b);
  lstm_k<<<128, 256>>>(W_hh_f, W_hh_b, h0, c0);
  feats_k<<<512, 256>>>(W_out, b_out);
  numer_k<<<128, 128>>>(tags, trans);
  denom_k<<<16, 256>>>(trans);
  mean_k<<<1, 128>>>(out);
}

// round 6
// speedup vs baseline: 1.0043x; 1.0043x over previous
#include <cuda_runtime.h>
#include <cuda_bf16.h>
#include <math.h>

#define SS 512
#define BB 128
#define EE 128
#define HH 128
#define KK 32
#define TAG_START 30
#define TAG_END 31

// ----------------------------- device scratch ------------------------------
__device__ float g_xW[(size_t)SS * BB * 1024];   // [s*B+b][d*512 + g*128 + u]
__device__ float g_hs[2][(size_t)SS * BB * HH];  // per-dir h at original time
__device__ float g_feats[(size_t)BB * SS * KK];  // [b][s][k]
__device__ float g_num[BB];
__device__ float g_den[BB];

// ----------------------------- helpers -------------------------------------
__device__ __forceinline__ void fma2(unsigned long long& d, unsigned long long a,
                                     unsigned long long b) {
  asm("fma.rn.f32x2 %0, %1, %2, %0;" : "+l"(d) : "l"(a), "l"(b));
}
__device__ __forceinline__ unsigned long long pack2(float x, float y) {
  unsigned long long r;
  asm("mov.b64 %0, {%1, %2};" : "=l"(r) : "f"(x), "f"(y));
  return r;
}
__device__ __forceinline__ float plo(unsigned long long v) {
  return __uint_as_float((unsigned)v);
}
__device__ __forceinline__ float phi(unsigned long long v) {
  return __uint_as_float((unsigned)(v >> 32));
}
__device__ __forceinline__ float sigm(float x) {
  return __fdividef(1.f, 1.f + __expf(-x));
}
__device__ __forceinline__ float ftanh(float x) {
  float e = __expf(-2.f * fmaxf(x, -20.f));
  return __fdividef(1.f - e, 1.f + e);
}

#define CLUSTER_SYNC()                                              \
  do {                                                              \
    asm volatile("barrier.cluster.arrive.aligned;" ::: "memory");   \
    asm volatile("barrier.cluster.wait.aligned;" ::: "memory");     \
  } while (0)

// ------------- 1) fused embedding + input GEMM: xW = X @ Wih^T + b ---------
// M = S*B = 65536, N = 1024 (fwd 512 | bwd 512), K = 128.
// 128x64 block tile, 8x4 thread tile, f32x2 packed FMA.
// A is staged in smem pre-duplicated as (a,a) u64 so the inner loop has
// zero mov.b64 packs: 4 LDS.128 (A) + 1 LDS.128 (B) + 16 FFMA2 per k.
__global__ void __launch_bounds__(256) gemm_xw_k(
    const int* __restrict__ sentence, const float* __restrict__ table,
    const float* __restrict__ Wf, const float* __restrict__ Wb,
    const float* __restrict__ bihf, const float* __restrict__ bhhf,
    const float* __restrict__ bihb, const float* __restrict__ bhhb) {
  __shared__ __align__(16) unsigned long long As2[32 * 128];  // [k][m] dup
  __shared__ __align__(16) float Bs[32 * 68];                 // [k][n] padded
  int tid = threadIdx.x;
  int bm = blockIdx.x, bn = blockIdx.y;
  int r0 = bm * 128, n0 = bn * 64;
  int tx = tid & 15, ty = tid >> 4;

  // A loader: 2 threads per row, 16 k each
  int arow = tid >> 1, akh = (tid & 1) * 16;
  int r = r0 + arow;
  int s = r >> 7, b = r & 127;
  const float* asrc = table + (size_t)sentence[b * SS + s] * EE;
  // B loader: 4 threads per row, 8 k each
  int brow = tid >> 2, bkq = (tid & 3) * 8;
  int jg = n0 + brow;
  const float* wsrc = (jg < 512) ? Wf + (size_t)jg * EE
                                 : Wb + (size_t)(jg - 512) * EE;

  unsigned long long acc2[8][2];
#pragma unroll
  for (int i = 0; i < 8; i++) { acc2[i][0] = 0ull; acc2[i][1] = 0ull; }

  for (int kt = 0; kt < 4; kt++) {
    int kb = kt * 32;
#pragma unroll
    for (int q = 0; q < 4; q++) {
      float4 v = *(const float4*)(asrc + kb + akh + q * 4);
      As2[(akh + q * 4 + 0) * 128 + arow] = pack2(v.x, v.x);
      As2[(akh + q * 4 + 1) * 128 + arow] = pack2(v.y, v.y);
      As2[(akh + q * 4 + 2) * 128 + arow] = pack2(v.z, v.z);
      As2[(akh + q * 4 + 3) * 128 + arow] = pack2(v.w, v.w);
    }
#pragma unroll
    for (int q = 0; q < 2; q++) {
      float4 v = *(const float4*)(wsrc + kb + bkq + q * 4);
      Bs[(bkq + q * 4 + 0) * 68 + brow] = v.x;
      Bs[(bkq + q * 4 + 1) * 68 + brow] = v.y;
      Bs[(bkq + q * 4 + 2) * 68 + brow] = v.z;
      Bs[(bkq + q * 4 + 3) * 68 + brow] = v.w;
    }
    __syncthreads();
#pragma unroll
    for (int kk = 0; kk < 32; kk++) {
      ulonglong2 a01 = *(const ulonglong2*)&As2[kk * 128 + ty * 8 + 0];
      ulonglong2 a23 = *(const ulonglong2*)&As2[kk * 128 + ty * 8 + 2];
      ulonglong2 a45 = *(const ulonglong2*)&As2[kk * 128 + ty * 8 + 4];
      ulonglong2 a67 = *(const ulonglong2*)&As2[kk * 128 + ty * 8 + 6];
      ulonglong2 bp = *(const ulonglong2*)&Bs[kk * 68 + tx * 4];
      fma2(acc2[0][0], a01.x, bp.x); fma2(acc2[0][1], a01.x, bp.y);
      fma2(acc2[1][0], a01.y, bp.x); fma2(acc2[1][1], a01.y, bp.y);
      fma2(acc2[2][0], a23.x, bp.x); fma2(acc2[2][1], a23.x, bp.y);
      fma2(acc2[3][0], a23.y, bp.x); fma2(acc2[3][1], a23.y, bp.y);
      fma2(acc2[4][0], a45.x, bp.x); fma2(acc2[4][1], a45.x, bp.y);
      fma2(acc2[5][0], a45.y, bp.x); fma2(acc2[5][1], a45.y, bp.y);
      fma2(acc2[6][0], a67.x, bp.x); fma2(acc2[6][1], a67.x, bp.y);
      fma2(acc2[7][0], a67.y, bp.x); fma2(acc2[7][1], a67.y, bp.y);
    }
    __syncthreads();
  }
  float bias[4];
#pragma unroll
  for (int jj = 0; jj < 4; jj++) {
    int j = n0 + tx * 4 + jj;
    bias[jj] = (j < 512) ? (bihf[j] + bhhf[j]) : (bihb[j - 512] + bhhb[j - 512]);
  }
  int n = n0 + tx * 4;
#pragma unroll
  for (int ii = 0; ii < 8; ii++) {
    int m = r0 + ty * 8 + ii;
    float4 o;
    o.x = plo(acc2[ii][0]) + bias[0];
    o.y = phi(acc2[ii][0]) + bias[1];
    o.z = plo(acc2[ii][1]) + bias[2];
    o.w = phi(acc2[ii][1]) + bias[3];
    *(float4*)&g_xW[(size_t)m * 1024 + n] = o;
  }
}

// --------------- 2) bidirectional LSTM recurrence (cluster pairs) ----------
// 64 clusters of 2 CTAs; cluster = (dir, 4-batch tile); CTA = u-half.
// W_hh slice lives permanently in registers (128 floats/thread).
// Per-step sync: phase-parity mbarrier (8 local + 8 remote warp-leader
// arrivals) instead of barrier.cluster (~490cyc UCGABAR + L1D flush).
__global__ void __cluster_dims__(2, 1, 1) __launch_bounds__(256, 1) lstm_k(
    const float* __restrict__ Whhf, const float* __restrict__ Whhb,
    const float* __restrict__ h0, const float* __restrict__ c0) {
  __shared__ __align__(16) float hb[2][4 * 132];  // [parity][b_local*132 + u]
  __shared__ __align__(8) unsigned long long bar;
  int rank = blockIdx.x & 1;
  int cl = blockIdx.x >> 1;
  int d = cl >> 5;
  int b0 = (cl & 31) * 4;
  int tid = threadIdx.x;
  int lane = tid & 31;
  int wid = tid >> 5;
  int ks = lane >> 3;                 // k-slice / batch-local index 0..3
  int ulg = wid * 8 + (lane & 7);     // 0..63
  int u = rank * 64 + ulg;

  const float* Whh = d ? Whhb : Whhf;
  // register-resident weights: w2[g][i] covers k = ks*32 + 2i, 2i+1
  unsigned long long w2[4][16];
#pragma unroll
  for (int g = 0; g < 4; g++) {
    const float* wr = Whh + (size_t)(g * 128 + u) * 128 + ks * 32;
#pragma unroll
    for (int q = 0; q < 8; q++) {
      ulonglong2 v = *(const ulonglong2*)(wr + q * 4);
      w2[g][q * 2] = v.x;
      w2[g][q * 2 + 1] = v.y;
    }
  }
  // init h (full 128 u per batch, local copy)
  for (int i = tid; i < 512; i += 256) {
    int j = i >> 7, uu = i & 127;
    hb[0][j * 132 + uu] = h0[(d * BB + b0 + j) * HH + uu];
  }
  float c = c0[(d * BB + b0 + ks) * HH + u];

  unsigned hb_u32, bar_u32;
  asm("{ .reg .u64 t; cvta.to.shared.u64 t, %1; cvt.u32.u64 %0, t; }"
      : "=r"(hb_u32) : "l"(&hb[0][0]));
  asm("{ .reg .u64 t; cvta.to.shared.u64 t, %1; cvt.u32.u64 %0, t; }"
      : "=r"(bar_u32) : "l"(&bar));
  unsigned peer_base, peer_bar;
  asm("mapa.shared::cluster.u32 %0, %1, %2;"
      : "=r"(peer_base) : "r"(hb_u32), "r"(rank ^ 1));
  asm("mapa.shared::cluster.u32 %0, %1, %2;"
      : "=r"(peer_bar) : "r"(bar_u32), "r"(rank ^ 1));

  if (tid == 0) {
    asm volatile("mbarrier.init.shared.b64 [%0], 16;" :: "r"(bar_u32)
                 : "memory");
  }
  __syncthreads();
  CLUSTER_SYNC();  // mbarrier init visible cluster-wide before any arrive

  for (int t = 0; t < SS; t++) {
    const float* cur = hb[t & 1];
    int np = (t + 1) & 1;
    int tx = d ? (SS - 1 - t) : t;
    // prefetch xW (gate = ks) for 4 batches
    float xwv[4];
    const float* xwb =
        g_xW + ((size_t)tx * BB + b0) * 1024 + d * 512 + ks * 128 + u;
#pragma unroll
    for (int j = 0; j < 4; j++) xwv[j] = __ldcg(xwb + j * 1024);

    unsigned long long acc2[4][4];
#pragma unroll
    for (int j = 0; j < 4; j++)
#pragma unroll
      for (int g = 0; g < 4; g++) acc2[j][g] = 0ull;

#pragma unroll
    for (int q = 0; q < 8; q++) {
      int k = ks * 32 + q * 4;
      ulonglong2 hv[4];
#pragma unroll
      for (int j = 0; j < 4; j++)
        hv[j] = *(const ulonglong2*)&cur[j * 132 + k];
#pragma unroll
      for (int j = 0; j < 4; j++)
#pragma unroll
        for (int g = 0; g < 4; g++) {
          fma2(acc2[j][g], hv[j].x, w2[g][q * 2]);
          fma2(acc2[j][g], hv[j].y, w2[g][q * 2 + 1]);
        }
    }
    float acc[4][4];
#pragma unroll
    for (int j = 0; j < 4; j++)
#pragma unroll
      for (int g = 0; g < 4; g++) {
        float v = plo(acc2[j][g]) + phi(acc2[j][g]);
        if (g == ks) v += xwv[j];
        v += __shfl_xor_sync(0xffffffffu, v, 8);
        v += __shfl_xor_sync(0xffffffffu, v, 16);
        acc[j][g] = v;
      }
    // each lane handles batch j = ks
    float gate[4];
#pragma unroll
    for (int g = 0; g < 4; g++) {
      float a01 = (ks & 1) ? acc[1][g] : acc[0][g];
      float a23 = (ks & 1) ? acc[3][g] : acc[2][g];
      gate[g] = (ks & 2) ? a23 : a01;
    }
    float si = sigm(gate[0]);
    float sf = sigm(gate[1]);
    float tg = ftanh(gate[2]);
    float so = sigm(gate[3]);
    c = sf * c + si * tg;
    float h = so * ftanh(c);
    hb[np][ks * 132 + u] = h;
    unsigned pa = peer_base + (unsigned)(np * 528 + ks * 132 + u) * 4u;
    asm volatile("st.shared::cluster.f32 [%0], %1;" :: "r"(pa), "f"(h));
    g_hs[d][((size_t)tx * BB + b0 + ks) * HH + u] = h;

    // ---- mbarrier step sync ----
    __syncwarp();
    if (lane == 0) {
      asm volatile("mbarrier.arrive.release.cta.shared::cta.b64 _, [%0];"
                   :: "r"(bar_u32) : "memory");
      asm volatile(
          "mbarrier.arrive.release.cluster.shared::cluster.b64 _, [%0];"
          :: "r"(peer_bar) : "memory");
    }
    {
      unsigned parity = (unsigned)(t & 1);
      asm volatile(
          "{\n\t"
          ".reg .pred P;\n\t"
          "WL_%=:\n\t"
          "mbarrier.try_wait.parity.acquire.cluster.shared::cta.b64 P, [%0], %1, 0x989680;\n\t"
          "@P bra.uni WD_%=;\n\t"
          "bra.uni WL_%=;\n\t"
          "WD_%=:\n\t"
          "}"
          :: "r"(bar_u32), "r"(parity) : "memory");
    }
  }
}

// -------------- 3) feats = concat(hf,hb) @ Wout^T + bout -------------------
__global__ void __launch_bounds__(256) feats_k(const float* __restrict__ Wout,
                                               const float* __restrict__ bout) {
  __shared__ __align__(16) float Wsh[32 * 260];
  __shared__ float bsh[32];
  int s = blockIdx.x;
  int tid = threadIdx.x;
  for (int i = tid; i < 2048; i += 256) {
    int k = i >> 6, m4 = i & 63;
    float4 v = ((const float4*)Wout)[i];
    *(float4*)&Wsh[k * 260 + m4 * 4] = v;
  }
  if (tid < 32) bsh[tid] = bout[tid];
  __syncthreads();
  int k = tid & 31, b0 = tid >> 5;
  for (int bb = 0; bb < 16; bb++) {
    int b = b0 + bb * 8;
    const float4* hf = (const float4*)&g_hs[0][((size_t)s * BB + b) * HH];
    const float4* hb2 = (const float4*)&g_hs[1][((size_t)s * BB + b) * HH];
    float acc = bsh[k];
#pragma unroll 8
    for (int m4 = 0; m4 < 32; m4++) {
      float4 hv = hf[m4];
      float4 wv = *(const float4*)&Wsh[k * 260 + m4 * 4];
      acc += hv.x * wv.x + hv.y * wv.y + hv.z * wv.z + hv.w * wv.w;
    }
#pragma unroll 8
    for (int m4 = 0; m4 < 32; m4++) {
      float4 hv = hb2[m4];
      float4 wv = *(const float4*)&Wsh[k * 260 + 128 + m4 * 4];
      acc += hv.x * wv.x + hv.y * wv.y + hv.z * wv.z + hv.w * wv.w;
    }
    g_feats[((size_t)b * SS + s) * KK + k] = acc;
  }
}

// ----------------------------- 4) CRF numerator ----------------------------
__global__ void __launch_bounds__(128) numer_k(const int* __restrict__ tags,
                                               const float* __restrict__ T) {
  __shared__ float red[128];
  int b = blockIdx.x;
  int tid = threadIdx.x;
  float sum = 0.f;
  for (int s = tid; s < SS; s += 128) {
    int cur = tags[b * SS + s];
    int prev = (s == 0) ? TAG_START : tags[b * SS + s - 1];
    sum += T[prev * KK + cur] + g_feats[((size_t)b * SS + s) * KK + cur];
  }
  red[tid] = sum;
  __syncthreads();
  for (int off = 64; off > 0; off >>= 1) {
    if (tid < off) red[tid] += red[tid + off];
    __syncthreads();
  }
  if (tid == 0) g_num[b] = red[0] + T[tags[b * SS + SS - 1] * KK + TAG_END];
}

// ---------------------------- 5) CRF denominator ---------------------------
// one warp per batch row; lane = next-tag; alpha register-resident.
// Steps 1..511 use the exp-hoisted matvec form:
//   alpha'[n] = log( sum_p exp(alpha[p]-m) * expT[n][p] ) + m + feat[n]
// with expT precomputed in registers (exp(-10000) == 0 masks forbidden
// transitions exactly). Step 0 keeps the safe two-pass path (alpha spread
// is 1e4 there). Lane END goes -inf afterwards; it contributes exp->0,
// identical to the reference's effective contribution.
__global__ void __launch_bounds__(256) denom_k(const float* __restrict__ T) {
  __shared__ float Tsh[32 * 33];
  int tid = threadIdx.x;
  int lane = tid & 31;
  int warp = tid >> 5;
  int b = blockIdx.x * 8 + warp;
  for (int i = tid; i < 1024; i += 256) Tsh[(i >> 5) * 33 + (i & 31)] = T[i];
  __syncthreads();

  float alpha = (lane == TAG_START) ? 0.f : -10000.f;
  const float* Trow = &Tsh[lane * 33];

  // step 0: safe two-pass logsumexp over combined alpha+T
  {
    float feat = g_feats[(size_t)b * SS * KK + lane];
    float tmp[32];
    float m = -3.0e38f;
#pragma unroll
    for (int p = 0; p < 32; p++) {
      float ap = __shfl_sync(0xffffffffu, alpha, p);
      tmp[p] = ap + Trow[p];
      m = fmaxf(m, tmp[p]);
    }
    float sum = 0.f;
#pragma unroll
    for (int p = 0; p < 32; p++) sum += __expf(tmp[p] - m);
    alpha = __logf(sum) + m + feat;
  }

  // register-resident exp(T) row
  float rT[32];
#pragma unroll
  for (int p = 0; p < 32; p++) rT[p] = __expf(Trow[p]);

  for (int s = 1; s < SS; s++) {
    float feat = g_feats[((size_t)b * SS + s) * KK + lane];
    float m = alpha;
#pragma unroll
    for (int o = 16; o > 0; o >>= 1)
      m = fmaxf(m, __shfl_xor_sync(0xffffffffu, m, o));
    float E = __expf(alpha - m);
    float sum = 0.f;
#pragma unroll
    for (int p = 0; p < 32; p++)
      sum += __shfl_sync(0xffffffffu, E, p) * rT[p];
    alpha = __logf(sum) + m + feat;
  }
  float v = alpha + Tsh[lane * 33 + TAG_END];
  float m2 = v;
#pragma unroll
  for (int o = 16; o > 0; o >>= 1)
    m2 = fmaxf(m2, __shfl_xor_sync(0xffffffffu, m2, o));
  float s2 = __expf(v - m2);
#pragma unroll
  for (int o = 16; o > 0; o >>= 1) s2 += __shfl_xor_sync(0xffffffffu, s2, o);
  if (lane == 0) g_den[b] = __logf(s2) + m2;
}

// --------------------------------- 6) mean ---------------------------------
__global__ void __launch_bounds__(128) mean_k(float* __restrict__ out) {
  __shared__ float red[128];
  int tid = threadIdx.x;
  red[tid] = g_num[tid] - g_den[tid];
  __syncthreads();
  for (int off = 64; off > 0; off >>= 1) {
    if (tid < off) red[tid] += red[tid + off];
    __syncthreads();
  }
  if (tid == 0) out[0] = red[0] / 128.0f;
}

// ------------------------------- launcher ----------------------------------
extern "C" void kernel_launch(void* const* d_in, const int* in_sizes, int n_in,
                              void* d_out, int out_size) {
  const int*   sentence = (const int*)d_in[0];
  const int*   tags     = (const int*)d_in[1];
  const float* table    = (const float*)d_in[2];
  const float* W_ih_f   = (const float*)d_in[3];
  const float* W_hh_f   = (const float*)d_in[4];
  const float* b_ih_f   = (const float*)d_in[5];
  const float* b_hh_f   = (const float*)d_in[6];
  const float* W_ih_b   = (const float*)d_in[7];
  const float* W_hh_b   = (const float*)d_in[8];
  const float* b_ih_b   = (const float*)d_in[9];
  const float* b_hh_b   = (const float*)d_in[10];
  const float* W_out    = (const float*)d_in[11];
  const float* b_out    = (const float*)d_in[12];
  const float* trans    = (const float*)d_in[13];
  const float* h0       = (const float*)d_in[14];
  const float* c0       = (const float*)d_in[15];
  float* out = (float*)d_out;

  gemm_xw_k<<<dim3(512, 16), 256>>>(sentence, table, W_ih_f, W_ih_b,
                                    b_ih_f, b_hh_f, b_ih_b, b_hh_b);
  lstm_k<<<128, 256>>>(W_hh_f, W_hh_b, h0, c0);
  feats_k<<<512, 256>>>(W_out, b_out);
  numer_k<<<128, 128>>>(tags, trans);
  denom_k<<<16, 256>>>(trans);
  mean_k<<<1, 128>>>(out);
}